// round 16
// baseline (speedup 1.0000x reference)
#include <cuda_runtime.h>

// Problem constants (fixed shapes from reference)
#define NB_   512
#define B_    32
#define QH_   32
#define KVH_  8
#define G_    4          // GQA group: QH/KVH
#define D_    128
#define BS_   128
#define BPS_  16         // blocks per sequence
#define SCALE_ 0.08838834764831845f
#define CONSTV_ 10.0f
#define EPS_  1.1754943508222875e-38f

// Scratch + arrival counters (counters zero at load; winner resets -> deterministic replays)
static __device__ float g_pout[NB_ * KVH_ * G_ * D_];   // 8 MB
static __device__ float g_bsum[NB_ * KVH_ * G_];
static __device__ int   g_cnt[B_ * KVH_];

// ---- packed f32x2 helpers (Blackwell FFMA2 path) ----
__device__ __forceinline__ unsigned long long ffma2(unsigned long long a, unsigned long long b, unsigned long long c) {
    unsigned long long d;
    asm("fma.rn.f32x2 %0, %1, %2, %3;" : "=l"(d) : "l"(a), "l"(b), "l"(c));
    return d;
}
__device__ __forceinline__ unsigned long long fadd2(unsigned long long a, unsigned long long b) {
    unsigned long long d;
    asm("add.rn.f32x2 %0, %1, %2;" : "=l"(d) : "l"(a), "l"(b));
    return d;
}
__device__ __forceinline__ unsigned long long fpack2(float lo, float hi) {
    unsigned long long r;
    asm("mov.b64 %0, {%1, %2};" : "=l"(r) : "f"(lo), "f"(hi));
    return r;
}
__device__ __forceinline__ float2 funpack2(unsigned long long v) {
    float lo, hi;
    asm("mov.b64 {%0, %1}, %2;" : "=f"(lo), "=f"(hi) : "l"(v));
    return make_float2(lo, hi);
}
// streaming (evict-first) 16B load via compiler intrinsic
__device__ __forceinline__ ulonglong2 ldcs128(const float* p) {
    uint4 v = __ldcs((const uint4*)p);
    ulonglong2 r;
    r.x = ((unsigned long long)v.y << 32) | v.x;
    r.y = ((unsigned long long)v.w << 32) | v.z;
    return r;
}

#define REDF_STRIDE 513   // mod 32 == 1: QK partial stores land bank = dc + 8*sg, conflict-free
                          // 8*513*4 = 16416 B >= 16384 B needed by PV u64 reuse

// ---- main: one CTA per (block n, kv head). 128 threads, 3 CTAs/SM:
//      ~168-reg budget lets ptxas hoist ~4 QK token-iterations of loads
//      (16 LDG.128 in flight per thread region) -> +50% outstanding bytes/SM.
//      Single-pass QK, one softmax, V prefetch across sync, fused epilogue. ----
__global__ void __launch_bounds__(128, 3) pa_main(
    const float* __restrict__ query,        // [B, QH, D]
    const float* __restrict__ kcache,       // [NCB, BS, KVH, D]
    const float* __restrict__ vcache,       // [NCB, BS, KVH, D]
    const float* __restrict__ mapping,      // [NB, B] one-hot
    const float* __restrict__ bias,         // [NB, BS]
    const int*   __restrict__ blist,        // [NB]
    float* __restrict__ out)                // [B, QH, D]
{
    __shared__ float sm_q[G_ * D_];                       // 2 KB
    __shared__ float sm_bias[BS_];                        // 0.5 KB
    __shared__ unsigned long long sm_pp[G_ * BS_];        // 4 KB
    __shared__ __align__(16) float redf[8 * REDF_STRIDE]; // 16.4 KB; PV reuses as u64
    __shared__ float sm_hsum[G_];
    __shared__ int   sm_b;
    __shared__ float sm_m;
    __shared__ int   sm_last;

    const int t  = threadIdx.x;
    const int n  = blockIdx.x >> 3;
    const int kv = blockIdx.x & 7;

    // batch index from one-hot mapping row (warp 0)
    if (t < 32) {
        float m = mapping[n * B_ + t];
        unsigned msk = __ballot_sync(0xffffffffu, m > 0.5f);
        int bb = __ffs(msk) - 1;
        float mv = __shfl_sync(0xffffffffu, m, bb);
        if (t == 0) { sm_b = bb; sm_m = mv; }
    }
    if (t < G_) sm_hsum[t] = 0.0f;
    __syncthreads();
    const int   b    = sm_b;
    const float mval = sm_m;
    const int   phys = blist[n];

    // stage scaled q (4 heads contiguous) + bias
    {
        const float qs = SCALE_ * mval;
        const float* qsrc = query + (size_t)b * QH_ * D_ + (size_t)kv * G_ * D_;
        #pragma unroll
        for (int i = t; i < G_ * D_; i += 128) sm_q[i] = qs * qsrc[i];
        sm_bias[t] = bias[n * BS_ + t];
    }

    const float* kbase = kcache + ((size_t)phys * BS_ * KVH_ + kv) * D_;
    const float* vbase = vcache + ((size_t)phys * BS_ * KVH_ + kv) * D_;

    // ================= QK phase: single uninterrupted pass =================
    // thread = (dc 0..7: 16 d-elems at d = dc*4 + 32*i + j) x (sg 0..15: 8 tokens)
    const int dc = t & 7;
    const int sg = t >> 3;

    __syncthreads();   // sm_q / sm_bias ready

    // preload q for this thread's d-slice, all 4 heads (64 regs)
    ulonglong2 qr[G_][4];
    #pragma unroll
    for (int h = 0; h < G_; ++h)
        #pragma unroll
        for (int i = 0; i < 4; ++i)
            qr[h][i] = *(const ulonglong2*)&sm_q[h * D_ + dc * 4 + 32 * i];

    // 8 tokens per thread, 4 LDG.128 each = 32 loads in one unrolled stream;
    // accumulator folded to smem per token so live registers stay flat.
    #pragma unroll
    for (int sl = 0; sl < 8; ++sl) {
        const int s = sg * 8 + sl;
        const float* krow = kbase + (size_t)s * (KVH_ * D_);
        ulonglong2 kk[4];
        #pragma unroll
        for (int i = 0; i < 4; ++i)
            kk[i] = ldcs128(krow + dc * 4 + 32 * i);
        #pragma unroll
        for (int h = 0; h < G_; ++h) {
            unsigned long long a = 0ull;
            #pragma unroll
            for (int i = 0; i < 4; ++i) {
                a = ffma2(kk[i].x, qr[h][i].x, a);
                a = ffma2(kk[i].y, qr[h][i].y, a);
            }
            float2 f = funpack2(a);
            redf[dc * REDF_STRIDE + h * 128 + s] = f.x + f.y;   // bank = dc + 8*sg: conflict-free
        }
    }
    __syncthreads();

    // ================= softmax: all 128 tokens, one phase =================
    #pragma unroll
    for (int k2 = 0; k2 < 4; ++k2) {
        const int idx = t + 128 * k2;            // 0..511 -> (h, s)
        const int h   = idx >> 7;                // uniform per (warp, k2)
        const int s   = idx & 127;
        float sc = 0.0f;
        #pragma unroll
        for (int dcc = 0; dcc < 8; ++dcc) sc += redf[dcc * REDF_STRIDE + h * 128 + s];
        const float p = __expf(sc + sm_bias[s] - CONSTV_);
        sm_pp[h * 128 + s] = fpack2(p, p);
        float ps = p;
        #pragma unroll
        for (int o = 16; o; o >>= 1) ps += __shfl_xor_sync(0xffffffffu, ps, o);
        if ((t & 31) == 0) atomicAdd(&sm_hsum[h], ps);
    }

    // ================= PV phase =================
    // thread = (dg 0..15: d = dg*4..+3 and 64+dg*4..+3) x (sg2 0..7: 16 tokens)
    const int dg  = t & 15;
    const int sg2 = t >> 4;

    // prefetch first 2 V rows BEFORE the phase sync (register-only, no hazard)
    ulonglong2 pvlo[2], pvhi[2];
    #pragma unroll
    for (int pf = 0; pf < 2; ++pf) {
        const float* vr = vbase + (size_t)(sg2 * 16 + pf) * (KVH_ * D_);
        pvlo[pf] = ldcs128(vr + dg * 4);
        pvhi[pf] = ldcs128(vr + 64 + dg * 4);
    }

    __syncthreads();   // sm_pp + sm_hsum complete; redf free for PV reuse

    if (t < G_) g_bsum[(n * KVH_ + kv) * G_ + t] = sm_hsum[t];

    unsigned long long o2[G_][4];
    #pragma unroll
    for (int h = 0; h < G_; ++h)
        #pragma unroll
        for (int j = 0; j < 4; ++j) o2[h][j] = 0ull;

    // peeled: prefetched rows
    #pragma unroll
    for (int ss = 0; ss < 2; ++ss) {
        const int s = sg2 * 16 + ss;
        #pragma unroll
        for (int h = 0; h < G_; ++h) {
            const unsigned long long pp = sm_pp[h * BS_ + s];
            o2[h][0] = ffma2(pvlo[ss].x, pp, o2[h][0]);
            o2[h][1] = ffma2(pvlo[ss].y, pp, o2[h][1]);
            o2[h][2] = ffma2(pvhi[ss].x, pp, o2[h][2]);
            o2[h][3] = ffma2(pvhi[ss].y, pp, o2[h][3]);
        }
    }
    #pragma unroll 7
    for (int ss = 2; ss < 16; ++ss) {
        const int s = sg2 * 16 + ss;
        const float* vr = vbase + (size_t)s * (KVH_ * D_);
        ulonglong2 vlo = ldcs128(vr + dg * 4);
        ulonglong2 vhi = ldcs128(vr + 64 + dg * 4);
        #pragma unroll
        for (int h = 0; h < G_; ++h) {
            const unsigned long long pp = sm_pp[h * BS_ + s];
            o2[h][0] = ffma2(vlo.x, pp, o2[h][0]);
            o2[h][1] = ffma2(vlo.y, pp, o2[h][1]);
            o2[h][2] = ffma2(vhi.x, pp, o2[h][2]);
            o2[h][3] = ffma2(vhi.y, pp, o2[h][3]);
        }
    }
    __syncthreads();   // softmax readers of redf done before u64 reuse

    // write partials: sm_red[(sg2*4 + h)*64 + pr], pr = d/2
    unsigned long long* sm_red = (unsigned long long*)redf;
    #pragma unroll
    for (int h = 0; h < G_; ++h) {
        ulonglong2 w0; w0.x = o2[h][0]; w0.y = o2[h][1];
        ulonglong2 w1; w1.x = o2[h][2]; w1.y = o2[h][3];
        *(ulonglong2*)&sm_red[(sg2 * 4 + h) * 64 + dg * 2]      = w0;
        *(ulonglong2*)&sm_red[(sg2 * 4 + h) * 64 + 32 + dg * 2] = w1;
    }
    __syncthreads();

    // reduce over sg2 (8 partials), scale by mval, coalesced store to scratch
    #pragma unroll
    for (int k2 = 0; k2 < 2; ++k2) {
        const int idx = t + 128 * k2;        // 0..255 -> (h, d-pair)
        const int h   = idx >> 6;
        const int pr  = idx & 63;
        unsigned long long sum = sm_red[h * 64 + pr];
        #pragma unroll
        for (int g2 = 1; g2 < 8; ++g2)
            sum = fadd2(sum, sm_red[(g2 * 4 + h) * 64 + pr]);
        float2 f = funpack2(sum);
        float2 w = make_float2(f.x * mval, f.y * mval);
        *(float2*)&g_pout[((size_t)(n * KVH_ + kv) * G_ + h) * D_ + pr * 2] = w;
    }

    // ================= fused epilogue (threadfence reduction) =================
    __threadfence();
    if (t == 0) sm_last = atomicAdd(&g_cnt[b * KVH_ + kv], 1);
    __syncthreads();
    if (sm_last == BPS_ - 1) {
        if (t == 0) g_cnt[b * KVH_ + kv] = 0;   // reset for next launch/replay
        __threadfence();                         // acquire: see peers' partials

        const int d4 = t & 31;
        const int h  = t >> 5;
        const float* pb = g_pout + ((size_t)(b * BPS_ * KVH_ + kv) * G_ + h) * D_ + d4 * 4;
        const float* sb = g_bsum + (b * BPS_ * KVH_ + kv) * G_ + h;

        float4 acc = make_float4(0.f, 0.f, 0.f, 0.f);
        float s = 0.0f;
        #pragma unroll
        for (int j = 0; j < BPS_; ++j) {
            const float4 v = *(const float4*)(pb + (size_t)j * (KVH_ * G_ * D_));
            acc.x += v.x; acc.y += v.y; acc.z += v.z; acc.w += v.w;
            s += sb[j * (KVH_ * G_)];
        }
        const float inv = 1.0f / (s + EPS_);
        float4 r = make_float4(acc.x * inv, acc.y * inv, acc.z * inv, acc.w * inv);
        *(float4*)(out + (size_t)b * QH_ * D_ + (size_t)(kv * G_ + h) * D_ + d4 * 4) = r;
    }
}

extern "C" void kernel_launch(void* const* d_in, const int* in_sizes, int n_in,
                              void* d_out, int out_size) {
    const float* query   = (const float*)d_in[0];
    const float* kcache  = (const float*)d_in[1];
    const float* vcache  = (const float*)d_in[2];
    const float* mapping = (const float*)d_in[3];
    const float* bias    = (const float*)d_in[4];
    const int*   blist   = (const int*)d_in[5];
    float* out = (float*)d_out;

    pa_main<<<NB_ * KVH_, 128>>>(query, kcache, vcache, mapping, bias, blist, out);
}

// round 17
// speedup vs baseline: 1.0187x; 1.0187x over previous
#include <cuda_runtime.h>

// Problem constants (fixed shapes from reference)
#define NB_   512
#define B_    32
#define QH_   32
#define KVH_  8
#define G_    4          // GQA group: QH/KVH
#define D_    128
#define BS_   128
#define BPS_  16         // blocks per sequence
#define HBS_  64         // half-block tokens
#define SCALE_ 0.08838834764831845f
#define CONSTV_ 10.0f
#define EPS_  1.1754943508222875e-38f

// Scratch: per-(block,kv,half) partial outputs / exp-sums + arrival counters.
// Counters zero at load; winner resets -> deterministic across graph replays.
static __device__ float g_pout[NB_ * KVH_ * 2 * G_ * D_];   // 16 MB
static __device__ float g_bsum[NB_ * KVH_ * 2 * G_];
static __device__ int   g_cnt[B_ * KVH_];                   // 32 arrivals each

// ---- packed f32x2 helpers (Blackwell FFMA2 path) ----
__device__ __forceinline__ unsigned long long ffma2(unsigned long long a, unsigned long long b, unsigned long long c) {
    unsigned long long d;
    asm("fma.rn.f32x2 %0, %1, %2, %3;" : "=l"(d) : "l"(a), "l"(b), "l"(c));
    return d;
}
__device__ __forceinline__ unsigned long long fadd2(unsigned long long a, unsigned long long b) {
    unsigned long long d;
    asm("add.rn.f32x2 %0, %1, %2;" : "=l"(d) : "l"(a), "l"(b));
    return d;
}
__device__ __forceinline__ unsigned long long fpack2(float lo, float hi) {
    unsigned long long r;
    asm("mov.b64 %0, {%1, %2};" : "=l"(r) : "f"(lo), "f"(hi));
    return r;
}
__device__ __forceinline__ float2 funpack2(unsigned long long v) {
    float lo, hi;
    asm("mov.b64 {%0, %1}, %2;" : "=f"(lo), "=f"(hi) : "l"(v));
    return make_float2(lo, hi);
}
__device__ __forceinline__ ulonglong2 ldcs128(const float* p) {
    uint4 v = __ldcs((const uint4*)p);
    ulonglong2 r;
    r.x = ((unsigned long long)v.y << 32) | v.x;
    r.y = ((unsigned long long)v.w << 32) | v.z;
    return r;
}

#define REDF_STRIDE 257   // mod 32 == 1: QK partial stores bank = dc + 8*sg, conflict-free
                          // 8*257*4 = 8224 B >= 8192 B needed by PV u64 reuse

// ---- main: one CTA per (block n, kv head, half). 64 threads, 8 CTAs/SM.
//      Per-thread QK shape identical to proven best (8 tokens x 4 LDG.128). ----
__global__ void __launch_bounds__(64, 8) pa_main(
    const float* __restrict__ query,        // [B, QH, D]
    const float* __restrict__ kcache,       // [NCB, BS, KVH, D]
    const float* __restrict__ vcache,       // [NCB, BS, KVH, D]
    const float* __restrict__ mapping,      // [NB, B] one-hot
    const float* __restrict__ bias,         // [NB, BS]
    const int*   __restrict__ blist,        // [NB]
    float* __restrict__ out)                // [B, QH, D]
{
    __shared__ float sm_q[G_ * D_];                       // 2 KB
    __shared__ float sm_bias[HBS_];                       // 256 B
    __shared__ unsigned long long sm_pp[G_ * HBS_];       // 2 KB
    __shared__ __align__(16) float redf[8 * REDF_STRIDE]; // 8.2 KB; PV reuses as u64
    __shared__ float sm_hsum[G_];
    __shared__ int   sm_b;
    __shared__ float sm_m;
    __shared__ int   sm_last;

    const int t    = threadIdx.x;          // 0..63
    const int bid  = blockIdx.x;
    const int n    = bid >> 4;
    const int kv   = (bid >> 1) & 7;
    const int half = bid & 1;

    // batch index from one-hot mapping row (warp 0)
    if (t < 32) {
        float m = mapping[n * B_ + t];
        unsigned msk = __ballot_sync(0xffffffffu, m > 0.5f);
        int bb = __ffs(msk) - 1;
        float mv = __shfl_sync(0xffffffffu, m, bb);
        if (t == 0) { sm_b = bb; sm_m = mv; }
    }
    if (t < G_) sm_hsum[t] = 0.0f;
    __syncthreads();
    const int   b    = sm_b;
    const float mval = sm_m;
    const int   phys = blist[n];

    // stage scaled q (4 heads contiguous) + this half's bias
    {
        const float qs = SCALE_ * mval;
        const float* qsrc = query + (size_t)b * QH_ * D_ + (size_t)kv * G_ * D_;
        #pragma unroll
        for (int i = t; i < G_ * D_; i += 64) sm_q[i] = qs * qsrc[i];
        sm_bias[t] = bias[n * BS_ + half * HBS_ + t];
    }

    const float* kbase = kcache + ((size_t)phys * BS_ * KVH_ + kv) * D_ + (size_t)half * HBS_ * (KVH_ * D_);
    const float* vbase = vcache + ((size_t)phys * BS_ * KVH_ + kv) * D_ + (size_t)half * HBS_ * (KVH_ * D_);

    // ================= QK phase: single uninterrupted pass =================
    // thread = (dc 0..7: 16 d-elems at d = dc*4 + 32*i) x (sg 0..7: 8 tokens)
    const int dc = t & 7;
    const int sg = t >> 3;

    __syncthreads();   // sm_q / sm_bias ready

    ulonglong2 qr[G_][4];
    #pragma unroll
    for (int h = 0; h < G_; ++h)
        #pragma unroll
        for (int i = 0; i < 4; ++i)
            qr[h][i] = *(const ulonglong2*)&sm_q[h * D_ + dc * 4 + 32 * i];

    // 8 tokens per thread, 4 LDG.128 each, folded to smem per token
    #pragma unroll
    for (int sl = 0; sl < 8; ++sl) {
        const int s = sg * 8 + sl;                    // local token 0..63
        const float* krow = kbase + (size_t)s * (KVH_ * D_);
        ulonglong2 kk[4];
        #pragma unroll
        for (int i = 0; i < 4; ++i)
            kk[i] = ldcs128(krow + dc * 4 + 32 * i);
        #pragma unroll
        for (int h = 0; h < G_; ++h) {
            unsigned long long a = 0ull;
            #pragma unroll
            for (int i = 0; i < 4; ++i) {
                a = ffma2(kk[i].x, qr[h][i].x, a);
                a = ffma2(kk[i].y, qr[h][i].y, a);
            }
            float2 f = funpack2(a);
            redf[dc * REDF_STRIDE + h * HBS_ + s] = f.x + f.y;  // bank = dc + 8*sg
        }
    }
    __syncthreads();

    // ================= softmax: 64 tokens, h = loop index (warp-uniform) =====
    #pragma unroll
    for (int h = 0; h < G_; ++h) {
        float sc = 0.0f;
        #pragma unroll
        for (int dcc = 0; dcc < 8; ++dcc) sc += redf[dcc * REDF_STRIDE + h * HBS_ + t];
        const float p = __expf(sc + sm_bias[t] - CONSTV_);
        sm_pp[h * HBS_ + t] = fpack2(p, p);
        float ps = p;
        #pragma unroll
        for (int o = 16; o; o >>= 1) ps += __shfl_xor_sync(0xffffffffu, ps, o);
        if ((t & 31) == 0) atomicAdd(&sm_hsum[h], ps);
    }

    // ================= PV phase =================
    // thread = (dg 0..15: d = dg*4..+3, 64+dg*4..+3) x (sg2 0..3: 16 tokens)
    const int dg  = t & 15;
    const int sg2 = t >> 4;

    // prefetch first 2 V rows BEFORE the phase sync
    ulonglong2 pvlo[2], pvhi[2];
    #pragma unroll
    for (int pf = 0; pf < 2; ++pf) {
        const float* vr = vbase + (size_t)(sg2 * 16 + pf) * (KVH_ * D_);
        pvlo[pf] = ldcs128(vr + dg * 4);
        pvhi[pf] = ldcs128(vr + 64 + dg * 4);
    }

    __syncthreads();   // sm_pp + sm_hsum complete; redf free for PV reuse

    if (t < G_) g_bsum[((n * KVH_ + kv) * 2 + half) * G_ + t] = sm_hsum[t];

    unsigned long long o2[G_][4];
    #pragma unroll
    for (int h = 0; h < G_; ++h)
        #pragma unroll
        for (int j = 0; j < 4; ++j) o2[h][j] = 0ull;

    #pragma unroll
    for (int ss = 0; ss < 2; ++ss) {
        const int s = sg2 * 16 + ss;
        #pragma unroll
        for (int h = 0; h < G_; ++h) {
            const unsigned long long pp = sm_pp[h * HBS_ + s];
            o2[h][0] = ffma2(pvlo[ss].x, pp, o2[h][0]);
            o2[h][1] = ffma2(pvlo[ss].y, pp, o2[h][1]);
            o2[h][2] = ffma2(pvhi[ss].x, pp, o2[h][2]);
            o2[h][3] = ffma2(pvhi[ss].y, pp, o2[h][3]);
        }
    }
    #pragma unroll 7
    for (int ss = 2; ss < 16; ++ss) {
        const int s = sg2 * 16 + ss;
        const float* vr = vbase + (size_t)s * (KVH_ * D_);
        ulonglong2 vlo = ldcs128(vr + dg * 4);
        ulonglong2 vhi = ldcs128(vr + 64 + dg * 4);
        #pragma unroll
        for (int h = 0; h < G_; ++h) {
            const unsigned long long pp = sm_pp[h * HBS_ + s];
            o2[h][0] = ffma2(vlo.x, pp, o2[h][0]);
            o2[h][1] = ffma2(vlo.y, pp, o2[h][1]);
            o2[h][2] = ffma2(vhi.x, pp, o2[h][2]);
            o2[h][3] = ffma2(vhi.y, pp, o2[h][3]);
        }
    }
    __syncthreads();   // all redf readers done before u64 reuse

    // write partials: sm_red[(sg2*4 + h)*64 + pr], pr = d/2; sg2 in 0..3
    unsigned long long* sm_red = (unsigned long long*)redf;
    #pragma unroll
    for (int h = 0; h < G_; ++h) {
        ulonglong2 w0; w0.x = o2[h][0]; w0.y = o2[h][1];
        ulonglong2 w1; w1.x = o2[h][2]; w1.y = o2[h][3];
        *(ulonglong2*)&sm_red[(sg2 * 4 + h) * 64 + dg * 2]      = w0;
        *(ulonglong2*)&sm_red[(sg2 * 4 + h) * 64 + 32 + dg * 2] = w1;
    }
    __syncthreads();

    // reduce over sg2 (4 partials), scale by mval, store to scratch
    #pragma unroll
    for (int h = 0; h < G_; ++h) {          // h warp-uniform; pr = t
        unsigned long long sum = sm_red[h * 64 + t];
        #pragma unroll
        for (int g2 = 1; g2 < 4; ++g2)
            sum = fadd2(sum, sm_red[(g2 * 4 + h) * 64 + t]);
        float2 f = funpack2(sum);
        float2 w = make_float2(f.x * mval, f.y * mval);
        *(float2*)&g_pout[(((size_t)(n * KVH_ + kv) * 2 + half) * G_ + h) * D_ + t * 2] = w;
    }

    // ================= fused epilogue (threadfence reduction) =================
    __threadfence();
    if (t == 0) sm_last = atomicAdd(&g_cnt[b * KVH_ + kv], 1);
    __syncthreads();
    if (sm_last == 2 * BPS_ - 1) {
        if (t == 0) g_cnt[b * KVH_ + kv] = 0;   // reset for next launch/replay
        __threadfence();                         // acquire: see peers' partials

        // 512 outputs = 128 float4; 64 threads x 2
        #pragma unroll
        for (int k2 = 0; k2 < 2; ++k2) {
            const int idx = t + 64 * k2;        // 0..127
            const int d4  = idx & 31;
            const int h   = idx >> 5;
            const float* pb = g_pout + ((size_t)(b * BPS_ * KVH_ + kv) * 2 * G_ + h) * D_ + d4 * 4;
            const float* sb = g_bsum + (b * BPS_ * KVH_ + kv) * 2 * G_ + h;

            float4 acc = make_float4(0.f, 0.f, 0.f, 0.f);
            float s = 0.0f;
            #pragma unroll
            for (int j = 0; j < 2 * BPS_; ++j) {
                // j = nn*2 + half: pout stride per nn = KVH_*2*G_*D_, per half = G_*D_
                const size_t off = (size_t)(j >> 1) * (KVH_ * 2 * G_ * D_) + (size_t)(j & 1) * (G_ * D_);
                const float4 v = *(const float4*)(pb + off);
                acc.x += v.x; acc.y += v.y; acc.z += v.z; acc.w += v.w;
                s += sb[(j >> 1) * (KVH_ * 2 * G_) + (j & 1) * G_];
            }
            const float inv = 1.0f / (s + EPS_);
            float4 r = make_float4(acc.x * inv, acc.y * inv, acc.z * inv, acc.w * inv);
            *(float4*)(out + (size_t)b * QH_ * D_ + (size_t)(kv * G_ + h) * D_ + d4 * 4) = r;
        }
    }
}

extern "C" void kernel_launch(void* const* d_in, const int* in_sizes, int n_in,
                              void* d_out, int out_size) {
    const float* query   = (const float*)d_in[0];
    const float* kcache  = (const float*)d_in[1];
    const float* vcache  = (const float*)d_in[2];
    const float* mapping = (const float*)d_in[3];
    const float* bias    = (const float*)d_in[4];
    const int*   blist   = (const int*)d_in[5];
    float* out = (float*)d_out;

    pa_main<<<NB_ * KVH_ * 2, 64>>>(query, kcache, vcache, mapping, bias, blist, out);
}